// round 12
// baseline (speedup 1.0000x reference)
#include <cuda_runtime.h>
#include <cuda_bf16.h>
#include <cuda_pipeline.h>
#include <math.h>

#define VOCAB 50000
#define D 256
#define Bn 128
#define Sn 64
#define Ln 32
#define Kn 32

// Scratch (device globals: allocation-free rule)
__device__ float  g_enc [Bn * Sn * D];          // enc_sents   (B,S,D)
__device__ float  g_encW[Bn * Sn * D];          // enc_sents@W (B,S,D)
__device__ float  g_keysV[Bn * Kn * D];         // keys@V      (B,K,D)
__device__ float  g_eK  [Bn * Sn * Kn];         // enc·keys    (B,S,K)
__device__ float2 g_Upk [(D / 2) * D];          // U packed: [p][c] = (U[2p][c], U[2p+1][c])

#define FMA_F32X2(d_, a_, b_, c_) \
    asm("fma.rn.f32x2 %0, %1, %2, %3;" : "=l"(d_) : "l"(a_), "l"(b_), "l"(c_))

// ---------------------------------------------------------------------------
// Fused: enc_sents[b,s,d] = sum_l emb[prgrph[b,s,l], d]
//        eK[b,s,k]        = sum_d enc[b,s,d] * keys[b,k,d]
// ---------------------------------------------------------------------------
__global__ void gather_eK_kernel(const int* __restrict__ prgrph,
                                 const float* __restrict__ emb,
                                 const float* __restrict__ keys) {
    __shared__ int   sidx[Ln];
    __shared__ float e_sh[D];
    int bs = blockIdx.x;
    int b  = bs / Sn;
    int t  = threadIdx.x;
    int w  = t >> 5, lane = t & 31;
    if (t < Ln) sidx[t] = prgrph[(size_t)bs * Ln + t];
    __syncthreads();
    float acc = 0.f;
#pragma unroll
    for (int l = 0; l < Ln; ++l) acc += __ldg(emb + (size_t)sidx[l] * D + t);
    g_enc[(size_t)bs * D + t] = acc;
    e_sh[t] = acc;
    __syncthreads();
#pragma unroll
    for (int r = 0; r < 4; ++r) {
        int k = w * 4 + r;
        const float* kr = keys + ((size_t)b * Kn + k) * D;
        float p = 0.f;
#pragma unroll
        for (int j = 0; j < 8; ++j) {
            int c = lane + 32 * j;
            p = fmaf(e_sh[c], __ldg(kr + c), p);
        }
#pragma unroll
        for (int o = 16; o > 0; o >>= 1) p += __shfl_xor_sync(0xffffffffu, p, o);
        if (lane == 0) g_eK[(size_t)bs * Kn + k] = p;
    }
}

// ---------------------------------------------------------------------------
__global__ void packU_kernel(const float* __restrict__ U) {
    int p = blockIdx.x;
    int c = threadIdx.x;
    g_Upk[p * D + c] = make_float2(U[(2 * p) * D + c], U[(2 * p + 1) * D + c]);
}

// ---------------------------------------------------------------------------
// 16-row GEMM tile: C[16,D] = A[16,D] @ Bm[D,D]
// ---------------------------------------------------------------------------
__device__ __forceinline__ void gemm16_body(const float* __restrict__ Ab,
                                            const float* __restrict__ Bm,
                                            float* __restrict__ Cb) {
    __shared__ float a_sh[16 * D];
    int t = threadIdx.x;
    for (int i = t; i < 16 * D; i += 256) a_sh[i] = Ab[i];
    __syncthreads();

    float acc[16];
#pragma unroll
    for (int k = 0; k < 16; ++k) acc[k] = 0.f;

    for (int d0 = 0; d0 < D; d0 += 8) {
        float u[8];
#pragma unroll
        for (int i = 0; i < 8; ++i) u[i] = __ldg(Bm + (size_t)(d0 + i) * D + t);
#pragma unroll
        for (int k = 0; k < 16; ++k) {
            float4 h1 = *(const float4*)&a_sh[k * D + d0];
            float4 h2 = *(const float4*)&a_sh[k * D + d0 + 4];
            acc[k] = fmaf(h1.x, u[0], acc[k]); acc[k] = fmaf(h1.y, u[1], acc[k]);
            acc[k] = fmaf(h1.z, u[2], acc[k]); acc[k] = fmaf(h1.w, u[3], acc[k]);
            acc[k] = fmaf(h2.x, u[4], acc[k]); acc[k] = fmaf(h2.y, u[5], acc[k]);
            acc[k] = fmaf(h2.z, u[6], acc[k]); acc[k] = fmaf(h2.w, u[7], acc[k]);
        }
    }
#pragma unroll
    for (int k = 0; k < 16; ++k) Cb[k * D + t] = acc[k];
}

// encW tiles (0..511) + keysV tiles (512..767)
__global__ void gemm_pre_kernel(const float* __restrict__ keys,
                                const float* __restrict__ V,
                                const float* __restrict__ W) {
    int blk = blockIdx.x;
    if (blk < 512) {
        size_t off = (size_t)blk * 16 * D;
        gemm16_body(g_enc + off, W, g_encW + off);
    } else {
        size_t off = (size_t)(blk - 512) * 16 * D;
        gemm16_body(keys + off, V, g_keysV + off);
    }
}

// ---------------------------------------------------------------------------
// The scan. 256 CTAs = (batch, 16-row half). 256 threads, 2 CTAs/SM.
// Warp w, lane l: colpair cp = 16w + (l&15); d-half lh = l>>4.
// GEMM: all 16 rows x 2 adjacent cols over own d-half (64 packed pairs),
//       U staged through smem via cp.async (8 chunks x 32KB, double-buffered,
//       cyclic across steps). d-half partials combined via shfl_xor(16).
// Epilogue: rows (lh?8:0)..+7 x 2 cols; fused next-gate dot + row norm.
// h kept UNNORMALIZED in smem; rs folded into gate/epilogue/output.
// ---------------------------------------------------------------------------
#define KH   16
#define NCH  8                        // chunks per step
#define CHB  (16 * 2048)              // 32KB: 16 pair-rows (8 per half) x 2KB

__global__ void __launch_bounds__(256, 2)
scan_kernel(const int* __restrict__ pmask,
            float* __restrict__ out) {
    extern __shared__ float sm[];
    float* h       = sm;                          // KH*D floats (16KB)
    char*  ubuf    = (char*)(h + KH * D);         // 2 x 32KB
    float* gate_sh = (float*)(ubuf + 2 * CHB);    // 16
    float* rs_sh   = gate_sh + KH;                // 16
    float* np_sh   = rs_sh + KH;                  // 16*8
    float* gd_sh   = np_sh + KH * 8;              // 16*8
    int*   nxt     = (int*)(gd_sh + KH * 8);      // Sn+1

    const int b    = blockIdx.x >> 1;
    const int half = blockIdx.x & 1;
    const int kgbl = half * KH;
    const int t    = threadIdx.x;
    const int w    = t >> 5;
    const int lane = t & 31;
    const int lh   = lane >> 4;        // d-half of this lane
    const int ll   = lane & 15;
    const int cp   = w * 16 + ll;      // colpair 0..127
    const int c0   = cp * 2;
    const int rb   = lh * 8;           // epilogue rows rb..rb+7

    const size_t encRow = (size_t)b * Sn;

    if (t == 0) {
        int n = -1;
        for (int s = Sn - 1; s >= 0; --s) {
            nxt[s] = n;
            if (pmask[(encRow + s) * Ln] != 0) n = s;
        }
        nxt[Sn] = n;
    }
    float kvA[8], kvB[8];
#pragma unroll
    for (int j = 0; j < 8; ++j) {
        float2 kv = __ldg((const float2*)
            (g_keysV + ((size_t)b * Kn + kgbl + rb + j) * D + c0));
        kvA[j] = kv.x; kvB[j] = kv.y;
    }
    for (int i = t; i < KH * D; i += 256) h[i] = 0.f;
    if (t < KH) rs_sh[t] = 1.f;
    __syncthreads();

    int s = nxt[Sn];
    if (s >= 0 && t < KH) {   // first gate: h=0 -> sigmoid(eK)
        float ek = __ldg(g_eK + (encRow + s) * Kn + kgbl + t);
        gate_sh[t] = 1.f / (1.f + expf(-ek));
    }
    __syncthreads();

    const char* Usrc = (const char*)g_Upk;   // row p at p*2048, col cp at +cp*16

    // prefetch chunk 0 into buf 0
#pragma unroll
    for (int i = 0; i < 8; ++i) {
        int u    = t + i * 256;                         // 16B unit 0..2047
        int brow = u >> 7;
        int off  = u & 127;
        int grow = (brow < 8) ? brow : 64 + (brow - 8); // chunk 0
        __pipeline_memcpy_async(ubuf + u * 16,
                                Usrc + (size_t)grow * 2048 + off * 16, 16);
    }
    __pipeline_commit();

    while (s >= 0) {
        const int snext = nxt[s];

        unsigned long long accA[16], accB[16];
#pragma unroll
        for (int r = 0; r < 16; ++r) { accA[r] = 0ull; accB[r] = 0ull; }

#pragma unroll
        for (int ch = 0; ch < NCH; ++ch) {
            __pipeline_wait_prior(0);
            __syncthreads();              // chunk ch resident; buffers safe
            {   // prefetch chunk (ch+1)&7 into the other buffer (cyclic)
                char* dst = ubuf + (((ch + 1) & 1) * CHB);
                const int cn = (ch + 1) & 7;
#pragma unroll
                for (int i = 0; i < 8; ++i) {
                    int u    = t + i * 256;
                    int brow = u >> 7;
                    int off  = u & 127;
                    int grow = (brow < 8) ? cn * 8 + brow
                                          : 64 + cn * 8 + (brow - 8);
                    __pipeline_memcpy_async(dst + u * 16,
                        Usrc + (size_t)grow * 2048 + off * 16, 16);
                }
                __pipeline_commit();
            }

            const char* usm = ubuf + ((ch & 1) * CHB);
            const int hbase = (lh * 64 + ch * 8) * 2;   // float offset in row

#pragma unroll
            for (int j4 = 0; j4 < 8; j4 += 4) {
                const char* ub = usm + (size_t)(lh * 8 + j4) * 2048 + cp * 16;
                ulonglong2 u0 = *(const ulonglong2*)(ub);
                ulonglong2 u1 = *(const ulonglong2*)(ub + 2048);
                ulonglong2 u2 = *(const ulonglong2*)(ub + 4096);
                ulonglong2 u3 = *(const ulonglong2*)(ub + 6144);
#pragma unroll
                for (int r = 0; r < 16; ++r) {
                    const ulonglong2* hp =
                        (const ulonglong2*)&h[r * D + hbase + j4 * 2];
                    ulonglong2 h01 = hp[0];
                    ulonglong2 h23 = hp[1];
                    FMA_F32X2(accA[r], h01.x, u0.x, accA[r]);
                    FMA_F32X2(accB[r], h01.x, u0.y, accB[r]);
                    FMA_F32X2(accA[r], h01.y, u1.x, accA[r]);
                    FMA_F32X2(accB[r], h01.y, u1.y, accB[r]);
                    FMA_F32X2(accA[r], h23.x, u2.x, accA[r]);
                    FMA_F32X2(accB[r], h23.x, u2.y, accB[r]);
                    FMA_F32X2(accA[r], h23.y, u3.x, accA[r]);
                    FMA_F32X2(accB[r], h23.y, u3.y, accB[r]);
                }
            }
        }

        // combine d-half partials with partner lane (lane ^ 16)
        float sA[16], sB[16];
#pragma unroll
        for (int r = 0; r < 16; ++r) {
            float2 aA = *(float2*)&accA[r];
            float2 aB = *(float2*)&accB[r];
            sA[r] = aA.x + aA.y;
            sB[r] = aB.x + aB.y;
        }
#pragma unroll
        for (int r = 0; r < 16; ++r) {
            sA[r] += __shfl_xor_sync(0xffffffffu, sA[r], 16);
            sB[r] += __shfl_xor_sync(0xffffffffu, sB[r], 16);
        }
        __syncthreads();   // S1: all old-h reads done; gate_sh/rs_sh stable

        // ---- epilogue: rows rb..rb+7 x 2 cols ----
        const float2 ew = __ldg((const float2*)(g_encW + (encRow + s) * D + c0));
        float2 en = make_float2(0.f, 0.f);
        if (snext >= 0)
            en = __ldg((const float2*)(g_enc + (encRow + snext) * D + c0));

        float np[8], gd[8];
#pragma unroll
        for (int j = 0; j < 8; ++j) {
            int   r  = rb + j;
            float rs = rs_sh[r];
            float gt = gate_sh[r];
            float2 hold = *(float2*)&h[r * D + c0];
            float htA = fmaxf(fmaf(rs, sA[r], kvA[j] + ew.x), 0.f);
            float htB = fmaxf(fmaf(rs, sB[r], kvB[j] + ew.y), 0.f);
            float hA = fmaf(gt, htA, rs * hold.x);
            float hB = fmaf(gt, htB, rs * hold.y);
            *(float2*)&h[r * D + c0] = make_float2(hA, hB);
            np[j] = fmaf(hA, hA, hB * hB);
            gd[j] = fmaf(en.x, hA, en.y * hB);
        }
        // reduce over the 16 lanes of own half (offsets 1,2,4,8)
#pragma unroll
        for (int o = 8; o > 0; o >>= 1) {
#pragma unroll
            for (int j = 0; j < 8; ++j) {
                np[j] += __shfl_xor_sync(0xffffffffu, np[j], o);
                gd[j] += __shfl_xor_sync(0xffffffffu, gd[j], o);
            }
        }
        if (ll == 0) {
#pragma unroll
            for (int j = 0; j < 8; ++j) {
                np_sh[(rb + j) * 8 + w] = np[j];
                gd_sh[(rb + j) * 8 + w] = gd[j];
            }
        }
        __syncthreads();   // S2: partials + new h visible

        if (t < KH) {
            float ssum = 0.f, gsum = 0.f;
#pragma unroll
            for (int q = 0; q < 8; ++q) {
                ssum += np_sh[t * 8 + q];
                gsum += gd_sh[t * 8 + q];
            }
            float rs = rsqrtf(fmaxf(ssum, 1e-12f));
            rs_sh[t] = rs;
            if (snext >= 0) {
                float ek = __ldg(g_eK + (encRow + snext) * Kn + kgbl + t);
                gate_sh[t] = 1.f / (1.f + expf(-(fmaf(rs, gsum, ek))));
            }
        }
        s = snext;
        // rs/gate writes ordered vs consumers by next step's chunk barrier.
    }

    __syncthreads();   // final rs_sh / h visibility
    for (int i = t; i < KH * D; i += 256) {
        int r = i >> 8;
        out[((size_t)b * Kn + kgbl) * D + i] = h[i] * rs_sh[r];
    }
}

// ---------------------------------------------------------------------------
extern "C" void kernel_launch(void* const* d_in, const int* in_sizes, int n_in,
                              void* d_out, int out_size) {
    const int*   prgrph = (const int*)d_in[0];
    const int*   pmask  = (const int*)d_in[1];
    const float* keys   = (const float*)d_in[2];
    const float* emb    = (const float*)d_in[3];
    const float* U      = (const float*)d_in[4];
    const float* V      = (const float*)d_in[5];
    const float* W      = (const float*)d_in[6];
    float*       out    = (float*)d_out;

    const int scan_smem = KH * D * 4 + 2 * CHB +
                          (2 * KH + 16 * KH) * 4 + (Sn + 1) * 4 + 64;
    cudaFuncSetAttribute(scan_kernel, cudaFuncAttributeMaxDynamicSharedMemorySize,
                         scan_smem);

    gather_eK_kernel<<<Bn * Sn, 256>>>(prgrph, emb, keys);
    packU_kernel<<<D / 2, 256>>>(U);
    gemm_pre_kernel<<<768, 256>>>(keys, V, W);
    scan_kernel<<<Bn * 2, 256, scan_smem>>>(pmask, out);
}

// round 13
// speedup vs baseline: 1.1163x; 1.1163x over previous
#include <cuda_runtime.h>
#include <cuda_bf16.h>
#include <math.h>

#define VOCAB 50000
#define D 256
#define Bn 128
#define Sn 64
#define Ln 32
#define Kn 32

// Scratch (device globals: allocation-free rule)
__device__ float  g_enc [Bn * Sn * D];          // enc_sents   (B,S,D)
__device__ float  g_encW[Bn * Sn * D];          // enc_sents@W (B,S,D)
__device__ float  g_keysV[Bn * Kn * D];         // keys@V      (B,K,D)
__device__ float  g_eK  [Bn * Sn * Kn];         // enc·keys    (B,S,K)
__device__ float2 g_Upk [(D / 2) * D];          // U packed: [p][c] = (U[2p][c], U[2p+1][c])

#define FMA_F32X2(d_, a_, b_, c_) \
    asm("fma.rn.f32x2 %0, %1, %2, %3;" : "=l"(d_) : "l"(a_), "l"(b_), "l"(c_))

// ---------------------------------------------------------------------------
// Fused: enc_sents[b,s,d] = sum_l emb[prgrph[b,s,l], d]
//        eK[b,s,k]        = sum_d enc[b,s,d] * keys[b,k,d]
// ---------------------------------------------------------------------------
__global__ void gather_eK_kernel(const int* __restrict__ prgrph,
                                 const float* __restrict__ emb,
                                 const float* __restrict__ keys) {
    __shared__ int   sidx[Ln];
    __shared__ float e_sh[D];
    int bs = blockIdx.x;
    int b  = bs / Sn;
    int t  = threadIdx.x;
    int w  = t >> 5, lane = t & 31;
    if (t < Ln) sidx[t] = prgrph[(size_t)bs * Ln + t];
    __syncthreads();
    float acc = 0.f;
#pragma unroll
    for (int l = 0; l < Ln; ++l) acc += __ldg(emb + (size_t)sidx[l] * D + t);
    g_enc[(size_t)bs * D + t] = acc;
    e_sh[t] = acc;
    __syncthreads();
#pragma unroll
    for (int r = 0; r < 4; ++r) {
        int k = w * 4 + r;
        const float* kr = keys + ((size_t)b * Kn + k) * D;
        float p = 0.f;
#pragma unroll
        for (int j = 0; j < 8; ++j) {
            int c = lane + 32 * j;
            p = fmaf(e_sh[c], __ldg(kr + c), p);
        }
#pragma unroll
        for (int o = 16; o > 0; o >>= 1) p += __shfl_xor_sync(0xffffffffu, p, o);
        if (lane == 0) g_eK[(size_t)bs * Kn + k] = p;
    }
}

// ---------------------------------------------------------------------------
__global__ void packU_kernel(const float* __restrict__ U) {
    int p = blockIdx.x;
    int c = threadIdx.x;
    g_Upk[p * D + c] = make_float2(U[(2 * p) * D + c], U[(2 * p + 1) * D + c]);
}

// ---------------------------------------------------------------------------
// 16-row GEMM tile: C[16,D] = A[16,D] @ Bm[D,D]
// ---------------------------------------------------------------------------
__device__ __forceinline__ void gemm16_body(const float* __restrict__ Ab,
                                            const float* __restrict__ Bm,
                                            float* __restrict__ Cb) {
    __shared__ float a_sh[16 * D];
    int t = threadIdx.x;
    for (int i = t; i < 16 * D; i += 256) a_sh[i] = Ab[i];
    __syncthreads();

    float acc[16];
#pragma unroll
    for (int k = 0; k < 16; ++k) acc[k] = 0.f;

    for (int d0 = 0; d0 < D; d0 += 8) {
        float u[8];
#pragma unroll
        for (int i = 0; i < 8; ++i) u[i] = __ldg(Bm + (size_t)(d0 + i) * D + t);
#pragma unroll
        for (int k = 0; k < 16; ++k) {
            float4 h1 = *(const float4*)&a_sh[k * D + d0];
            float4 h2 = *(const float4*)&a_sh[k * D + d0 + 4];
            acc[k] = fmaf(h1.x, u[0], acc[k]); acc[k] = fmaf(h1.y, u[1], acc[k]);
            acc[k] = fmaf(h1.z, u[2], acc[k]); acc[k] = fmaf(h1.w, u[3], acc[k]);
            acc[k] = fmaf(h2.x, u[4], acc[k]); acc[k] = fmaf(h2.y, u[5], acc[k]);
            acc[k] = fmaf(h2.z, u[6], acc[k]); acc[k] = fmaf(h2.w, u[7], acc[k]);
        }
    }
#pragma unroll
    for (int k = 0; k < 16; ++k) Cb[k * D + t] = acc[k];
}

// encW tiles (0..511) + keysV tiles (512..767)
__global__ void gemm_pre_kernel(const float* __restrict__ keys,
                                const float* __restrict__ V,
                                const float* __restrict__ W) {
    int blk = blockIdx.x;
    if (blk < 512) {
        size_t off = (size_t)blk * 16 * D;
        gemm16_body(g_enc + off, W, g_encW + off);
    } else {
        size_t off = (size_t)(blk - 512) * 16 * D;
        gemm16_body(keys + off, V, g_keysV + off);
    }
}

// ---------------------------------------------------------------------------
// The scan. 256 CTAs = (batch, 16-row half). 256 threads, 2 CTAs/SM.
// Warp w, lane l: colpair cp = 16w + (l&15); d-half lh = l>>4.
// GEMM: all 16 rows x 2 adjacent cols over own d-half (64 packed pairs),
//       U direct from L1/L2 via batched LDG.128 (8-pair blocks, MLP 8).
//       d-half partials combined via shfl_xor(16).
// Epilogue: rows (lh?8:0)..+7 x 2 cols; fused next-gate dot + row norm.
// Per-step scalar loads (ew/en/eK) hoisted above S1 to hide latency.
// h kept UNNORMALIZED in smem; rs folded into gate/epilogue/output.
// ---------------------------------------------------------------------------
#define KH 16

__global__ void __launch_bounds__(256, 2)
scan_kernel(const int* __restrict__ pmask,
            float* __restrict__ out) {
    __shared__ float h[KH * D];          // 16 KB, unnormalized local rows
    __shared__ float gate_sh[KH];
    __shared__ float rs_sh[KH];
    __shared__ float np_sh[KH * 8];
    __shared__ float gd_sh[KH * 8];
    __shared__ int   nxt[Sn + 1];

    const int b    = blockIdx.x >> 1;
    const int half = blockIdx.x & 1;
    const int kgbl = half * KH;
    const int t    = threadIdx.x;
    const int w    = t >> 5;
    const int lane = t & 31;
    const int lh   = lane >> 4;        // d-half of this lane
    const int ll   = lane & 15;
    const int cp   = w * 16 + ll;      // colpair 0..127
    const int c0   = cp * 2;
    const int rb   = lh * 8;           // epilogue rows rb..rb+7

    const size_t encRow = (size_t)b * Sn;

    if (t == 0) {
        int n = -1;
        for (int s = Sn - 1; s >= 0; --s) {
            nxt[s] = n;
            if (pmask[(encRow + s) * Ln] != 0) n = s;
        }
        nxt[Sn] = n;
    }
    float kvA[8], kvB[8];
#pragma unroll
    for (int j = 0; j < 8; ++j) {
        float2 kv = __ldg((const float2*)
            (g_keysV + ((size_t)b * Kn + kgbl + rb + j) * D + c0));
        kvA[j] = kv.x; kvB[j] = kv.y;
    }
    for (int i = t; i < KH * D; i += 256) h[i] = 0.f;
    if (t < KH) rs_sh[t] = 1.f;
    __syncthreads();

    int s = nxt[Sn];
    if (s >= 0 && t < KH) {   // first gate: h=0 -> sigmoid(eK)
        float ek = __ldg(g_eK + (encRow + s) * Kn + kgbl + t);
        gate_sh[t] = 1.f / (1.f + expf(-ek));
    }
    __syncthreads();

    const ulonglong2* Upk2 = (const ulonglong2*)g_Upk;  // [pair p][colpair cp]
    const int pbase = lh * 64;

    while (s >= 0) {
        const int snext = nxt[s];

        // ---- GEMM partial over own d-half: 16 rows x 2 cols x 64 pairs ----
        unsigned long long accA[16], accB[16];
#pragma unroll
        for (int r = 0; r < 16; ++r) { accA[r] = 0ull; accB[r] = 0ull; }

#pragma unroll
        for (int g8 = 0; g8 < 8; ++g8) {
            const int p0 = pbase + g8 * 8;
            ulonglong2 u0 = __ldg(Upk2 + (size_t)(p0 + 0) * 128 + cp);
            ulonglong2 u1 = __ldg(Upk2 + (size_t)(p0 + 1) * 128 + cp);
            ulonglong2 u2 = __ldg(Upk2 + (size_t)(p0 + 2) * 128 + cp);
            ulonglong2 u3 = __ldg(Upk2 + (size_t)(p0 + 3) * 128 + cp);
            ulonglong2 u4 = __ldg(Upk2 + (size_t)(p0 + 4) * 128 + cp);
            ulonglong2 u5 = __ldg(Upk2 + (size_t)(p0 + 5) * 128 + cp);
            ulonglong2 u6 = __ldg(Upk2 + (size_t)(p0 + 6) * 128 + cp);
            ulonglong2 u7 = __ldg(Upk2 + (size_t)(p0 + 7) * 128 + cp);
#pragma unroll
            for (int r = 0; r < 16; ++r) {
                const ulonglong2* hp = (const ulonglong2*)&h[r * D + p0 * 2];
                ulonglong2 h0 = hp[0], h1 = hp[1], h2 = hp[2], h3 = hp[3];
                FMA_F32X2(accA[r], h0.x, u0.x, accA[r]);
                FMA_F32X2(accB[r], h0.x, u0.y, accB[r]);
                FMA_F32X2(accA[r], h0.y, u1.x, accA[r]);
                FMA_F32X2(accB[r], h0.y, u1.y, accB[r]);
                FMA_F32X2(accA[r], h1.x, u2.x, accA[r]);
                FMA_F32X2(accB[r], h1.x, u2.y, accB[r]);
                FMA_F32X2(accA[r], h1.y, u3.x, accA[r]);
                FMA_F32X2(accB[r], h1.y, u3.y, accB[r]);
                FMA_F32X2(accA[r], h2.x, u4.x, accA[r]);
                FMA_F32X2(accB[r], h2.x, u4.y, accB[r]);
                FMA_F32X2(accA[r], h2.y, u5.x, accA[r]);
                FMA_F32X2(accB[r], h2.y, u5.y, accB[r]);
                FMA_F32X2(accA[r], h3.x, u6.x, accA[r]);
                FMA_F32X2(accB[r], h3.x, u6.y, accB[r]);
                FMA_F32X2(accA[r], h3.y, u7.x, accA[r]);
                FMA_F32X2(accB[r], h3.y, u7.y, accB[r]);
            }
        }

        // combine d-half partials with partner lane (lane ^ 16)
        float sA[16], sB[16];
#pragma unroll
        for (int r = 0; r < 16; ++r) {
            float2 aA = *(float2*)&accA[r];
            float2 aB = *(float2*)&accB[r];
            sA[r] = aA.x + aA.y;
            sB[r] = aB.x + aB.y;
        }
#pragma unroll
        for (int r = 0; r < 16; ++r) {
            sA[r] += __shfl_xor_sync(0xffffffffu, sA[r], 16);
            sB[r] += __shfl_xor_sync(0xffffffffu, sB[r], 16);
        }

        // ---- prefetch per-step scalars (latency hides under S1/epilogue) ----
        float ekn = 0.f;
        if (snext >= 0 && t < KH)
            ekn = __ldg(g_eK + (encRow + snext) * Kn + kgbl + t);
        const float2 ew = __ldg((const float2*)(g_encW + (encRow + s) * D + c0));
        float2 en = make_float2(0.f, 0.f);
        if (snext >= 0)
            en = __ldg((const float2*)(g_enc + (encRow + snext) * D + c0));

        __syncthreads();   // S1: all old-h reads done; gate_sh/rs_sh stable

        // ---- epilogue: rows rb..rb+7 x 2 cols ----
        float np[8], gd[8];
#pragma unroll
        for (int j = 0; j < 8; ++j) {
            int   r  = rb + j;
            float rs = rs_sh[r];
            float gt = gate_sh[r];
            float2 hold = *(float2*)&h[r * D + c0];
            float htA = fmaxf(fmaf(rs, sA[r], kvA[j] + ew.x), 0.f);
            float htB = fmaxf(fmaf(rs, sB[r], kvB[j] + ew.y), 0.f);
            float hA = fmaf(gt, htA, rs * hold.x);
            float hB = fmaf(gt, htB, rs * hold.y);
            *(float2*)&h[r * D + c0] = make_float2(hA, hB);
            np[j] = fmaf(hA, hA, hB * hB);
            gd[j] = fmaf(en.x, hA, en.y * hB);
        }
        // reduce over the 16 lanes of own half (offsets 8,4,2,1)
#pragma unroll
        for (int o = 8; o > 0; o >>= 1) {
#pragma unroll
            for (int j = 0; j < 8; ++j) {
                np[j] += __shfl_xor_sync(0xffffffffu, np[j], o);
                gd[j] += __shfl_xor_sync(0xffffffffu, gd[j], o);
            }
        }
        if (ll == 0) {
#pragma unroll
            for (int j = 0; j < 8; ++j) {
                np_sh[(rb + j) * 8 + w] = np[j];
                gd_sh[(rb + j) * 8 + w] = gd[j];
            }
        }
        __syncthreads();   // S2: partials + new h visible

        if (t < KH) {
            float ssum = 0.f, gsum = 0.f;
#pragma unroll
            for (int q = 0; q < 8; ++q) {
                ssum += np_sh[t * 8 + q];
                gsum += gd_sh[t * 8 + q];
            }
            float rs = rsqrtf(fmaxf(ssum, 1e-12f));
            rs_sh[t] = rs;
            if (snext >= 0)
                gate_sh[t] = 1.f / (1.f + expf(-(fmaf(rs, gsum, ekn))));
        }
        s = snext;
        // rs/gate writes ordered vs consumers by next step's S1.
    }

    __syncthreads();   // final rs_sh / h visibility
    for (int i = t; i < KH * D; i += 256) {
        int r = i >> 8;
        out[((size_t)b * Kn + kgbl) * D + i] = h[i] * rs_sh[r];
    }
}

// ---------------------------------------------------------------------------
extern "C" void kernel_launch(void* const* d_in, const int* in_sizes, int n_in,
                              void* d_out, int out_size) {
    const int*   prgrph = (const int*)d_in[0];
    const int*   pmask  = (const int*)d_in[1];
    const float* keys   = (const float*)d_in[2];
    const float* emb    = (const float*)d_in[3];
    const float* U      = (const float*)d_in[4];
    const float* V      = (const float*)d_in[5];
    const float* W      = (const float*)d_in[6];
    float*       out    = (float*)d_out;

    gather_eK_kernel<<<Bn * Sn, 256>>>(prgrph, emb, keys);
    packU_kernel<<<D / 2, 256>>>(U);
    gemm_pre_kernel<<<768, 256>>>(keys, V, W);
    scan_kernel<<<Bn * 2, 256>>>(pmask, out);
}

// round 14
// speedup vs baseline: 1.1835x; 1.0601x over previous
#include <cuda_runtime.h>
#include <cuda_bf16.h>
#include <math.h>

#define VOCAB 50000
#define D 256
#define Bn 128
#define Sn 64
#define Ln 32
#define Kn 32

// Scratch (device globals: allocation-free rule)
__device__ float  g_enc [Bn * Sn * D];          // enc_sents   (B,S,D)
__device__ float  g_encW[Bn * Sn * D];          // enc_sents@W (B,S,D)
__device__ float  g_keysV[Bn * Kn * D];         // keys@V      (B,K,D)
__device__ float  g_eK  [Bn * Sn * Kn];         // enc·keys    (B,S,K)
__device__ float2 g_Upk [(D / 2) * D];          // packed U: [p][c]=(U[2p][c],U[2p+1][c])
__device__ float2 g_Wpk [(D / 2) * D];          // packed W
__device__ float2 g_Vpk [(D / 2) * D];          // packed V

#define FMA_F32X2(d_, a_, b_, c_) \
    asm("fma.rn.f32x2 %0, %1, %2, %3;" : "=l"(d_) : "l"(a_), "l"(b_), "l"(c_))

// ---------------------------------------------------------------------------
// Fused: enc_sents[b,s,d] = sum_l emb[prgrph[b,s,l], d]
//        eK[b,s,k]        = sum_d enc[b,s,d] * keys[b,k,d]
// ---------------------------------------------------------------------------
__global__ void gather_eK_kernel(const int* __restrict__ prgrph,
                                 const float* __restrict__ emb,
                                 const float* __restrict__ keys) {
    __shared__ int   sidx[Ln];
    __shared__ float e_sh[D];
    int bs = blockIdx.x;
    int b  = bs / Sn;
    int t  = threadIdx.x;
    int w  = t >> 5, lane = t & 31;
    if (t < Ln) sidx[t] = prgrph[(size_t)bs * Ln + t];
    __syncthreads();
    float acc = 0.f;
#pragma unroll
    for (int l = 0; l < Ln; ++l) acc += __ldg(emb + (size_t)sidx[l] * D + t);
    g_enc[(size_t)bs * D + t] = acc;
    e_sh[t] = acc;
    __syncthreads();
#pragma unroll
    for (int r = 0; r < 4; ++r) {
        int k = w * 4 + r;
        const float* kr = keys + ((size_t)b * Kn + k) * D;
        float p = 0.f;
#pragma unroll
        for (int j = 0; j < 8; ++j) {
            int c = lane + 32 * j;
            p = fmaf(e_sh[c], __ldg(kr + c), p);
        }
#pragma unroll
        for (int o = 16; o > 0; o >>= 1) p += __shfl_xor_sync(0xffffffffu, p, o);
        if (lane == 0) g_eK[(size_t)bs * Kn + k] = p;
    }
}

// ---------------------------------------------------------------------------
// Pack U, W, V into float2 d-pairs: dst[p*D + c] = (M[2p][c], M[2p+1][c])
// ---------------------------------------------------------------------------
__global__ void pack_kernel(const float* __restrict__ U,
                            const float* __restrict__ W,
                            const float* __restrict__ V) {
    int p     = blockIdx.x & 127;
    int which = blockIdx.x >> 7;
    int c     = threadIdx.x;
    const float* M = (which == 0) ? U : (which == 1) ? W : V;
    float2* dst    = (which == 0) ? g_Upk : (which == 1) ? g_Wpk : g_Vpk;
    dst[p * D + c] = make_float2(M[(2 * p) * D + c], M[(2 * p + 1) * D + c]);
}

// ---------------------------------------------------------------------------
// 16-row GEMM tile in scan style: C[16,D] = A[16,D] @ B[D,D] (B packed f32x2)
// warp w lane l: colpair cp = 16w + (l&15), d-half lh = l>>4.
// ---------------------------------------------------------------------------
__device__ __forceinline__ void gemm16_f32x2(const float* __restrict__ Ab,
                                             const float2* __restrict__ Bpk,
                                             float* __restrict__ Cb) {
    __shared__ float a_sh[16 * D];
    const int t    = threadIdx.x;
    const int w    = t >> 5;
    const int lane = t & 31;
    const int lh   = lane >> 4;
    const int ll   = lane & 15;
    const int cp   = w * 16 + ll;
    const int c0   = cp * 2;
    const int rb   = lh * 8;
    const int pbase = lh * 64;

    for (int i = t; i < 16 * D; i += 256) a_sh[i] = Ab[i];
    __syncthreads();

    unsigned long long accA[16], accB[16];
#pragma unroll
    for (int r = 0; r < 16; ++r) { accA[r] = 0ull; accB[r] = 0ull; }

    const ulonglong2* B2 = (const ulonglong2*)Bpk;
#pragma unroll
    for (int g8 = 0; g8 < 8; ++g8) {
        const int p0 = pbase + g8 * 8;
        ulonglong2 u0 = __ldg(B2 + (size_t)(p0 + 0) * 128 + cp);
        ulonglong2 u1 = __ldg(B2 + (size_t)(p0 + 1) * 128 + cp);
        ulonglong2 u2 = __ldg(B2 + (size_t)(p0 + 2) * 128 + cp);
        ulonglong2 u3 = __ldg(B2 + (size_t)(p0 + 3) * 128 + cp);
        ulonglong2 u4 = __ldg(B2 + (size_t)(p0 + 4) * 128 + cp);
        ulonglong2 u5 = __ldg(B2 + (size_t)(p0 + 5) * 128 + cp);
        ulonglong2 u6 = __ldg(B2 + (size_t)(p0 + 6) * 128 + cp);
        ulonglong2 u7 = __ldg(B2 + (size_t)(p0 + 7) * 128 + cp);
#pragma unroll
        for (int r = 0; r < 16; ++r) {
            const ulonglong2* hp = (const ulonglong2*)&a_sh[r * D + p0 * 2];
            ulonglong2 h0 = hp[0], h1 = hp[1], h2 = hp[2], h3 = hp[3];
            FMA_F32X2(accA[r], h0.x, u0.x, accA[r]);
            FMA_F32X2(accB[r], h0.x, u0.y, accB[r]);
            FMA_F32X2(accA[r], h0.y, u1.x, accA[r]);
            FMA_F32X2(accB[r], h0.y, u1.y, accB[r]);
            FMA_F32X2(accA[r], h1.x, u2.x, accA[r]);
            FMA_F32X2(accB[r], h1.x, u2.y, accB[r]);
            FMA_F32X2(accA[r], h1.y, u3.x, accA[r]);
            FMA_F32X2(accB[r], h1.y, u3.y, accB[r]);
            FMA_F32X2(accA[r], h2.x, u4.x, accA[r]);
            FMA_F32X2(accB[r], h2.x, u4.y, accB[r]);
            FMA_F32X2(accA[r], h2.y, u5.x, accA[r]);
            FMA_F32X2(accB[r], h2.y, u5.y, accB[r]);
            FMA_F32X2(accA[r], h3.x, u6.x, accA[r]);
            FMA_F32X2(accB[r], h3.x, u6.y, accB[r]);
            FMA_F32X2(accA[r], h3.y, u7.x, accA[r]);
            FMA_F32X2(accB[r], h3.y, u7.y, accB[r]);
        }
    }

    float sA[16], sB[16];
#pragma unroll
    for (int r = 0; r < 16; ++r) {
        float2 aA = *(float2*)&accA[r];
        float2 aB = *(float2*)&accB[r];
        sA[r] = aA.x + aA.y;
        sB[r] = aB.x + aB.y;
    }
#pragma unroll
    for (int j = 0; j < 8; ++j) {
        float keepA = lh ? sA[8 + j] : sA[j];
        float sendA = lh ? sA[j]     : sA[8 + j];
        float keepB = lh ? sB[8 + j] : sB[j];
        float sendB = lh ? sB[j]     : sB[8 + j];
        float mA = keepA + __shfl_xor_sync(0xffffffffu, sendA, 16);
        float mB = keepB + __shfl_xor_sync(0xffffffffu, sendB, 16);
        *(float2*)&Cb[(rb + j) * D + c0] = make_float2(mA, mB);
    }
}

// encW tiles (0..511) + keysV tiles (512..767)
__global__ void gemm_pre_kernel(const float* __restrict__ keys) {
    int blk = blockIdx.x;
    if (blk < 512) {
        size_t off = (size_t)blk * 16 * D;
        gemm16_f32x2(g_enc + off, g_Wpk, g_encW + off);
    } else {
        size_t off = (size_t)(blk - 512) * 16 * D;
        gemm16_f32x2(keys + off, g_Vpk, g_keysV + off);
    }
}

// ---------------------------------------------------------------------------
// The scan. 256 CTAs = (batch, 16-row half). 256 threads, 2 CTAs/SM.
// Warp w lane l: colpair cp = 16w + (l&15); d-half lh = l>>4.
// Single __syncthreads per step:
//   - h double-buffered (GEMM reads h[p], epilogue writes h[p^1])
//   - np/gd partial buffers double-buffered by step parity
//   - rs/gate computed redundantly per warp from np/gd (benign identical-value
//     races on rs_sh/gate_sh), ordered by __syncwarp placed after the GEMM so
//     the eK load + expf latency hides under it.
// Partner-swap combine: 16 shfl_xor(16) instead of full 32-row exchange.
// h kept UNNORMALIZED; rs folded into gate/epilogue/output.
// ---------------------------------------------------------------------------
#define KH 16

__global__ void __launch_bounds__(256, 2)
scan_kernel(const int* __restrict__ pmask,
            float* __restrict__ out) {
    __shared__ float h[2][KH * D];        // 2 x 16 KB, unnormalized local rows
    __shared__ float np_sh[2][KH * 8];
    __shared__ float gd_sh[2][KH * 8];
    __shared__ float rs_sh[KH];           // benign-race (identical values)
    __shared__ float gate_sh[KH];
    __shared__ int   nxt[Sn + 1];

    const int b    = blockIdx.x >> 1;
    const int half = blockIdx.x & 1;
    const int kgbl = half * KH;
    const int t    = threadIdx.x;
    const int w    = t >> 5;
    const int lane = t & 31;
    const int lh   = lane >> 4;
    const int ll   = lane & 15;
    const int cp   = w * 16 + ll;
    const int c0   = cp * 2;
    const int rb   = lh * 8;
    const int pbase = lh * 64;

    const size_t encRow = (size_t)b * Sn;

    if (t == 0) {
        int n = -1;
        for (int s = Sn - 1; s >= 0; --s) {
            nxt[s] = n;
            if (pmask[(encRow + s) * Ln] != 0) n = s;
        }
        nxt[Sn] = n;
    }
    float kvA[8], kvB[8];
#pragma unroll
    for (int j = 0; j < 8; ++j) {
        float2 kv = __ldg((const float2*)
            (g_keysV + ((size_t)b * Kn + kgbl + rb + j) * D + c0));
        kvA[j] = kv.x; kvB[j] = kv.y;
    }
    for (int i = t; i < KH * D; i += 256) h[0][i] = 0.f;
    for (int i = t; i < KH * 8; i += 256) { np_sh[0][i] = 0.125f; gd_sh[0][i] = 0.f; }
    __syncthreads();

    int s   = nxt[Sn];
    int p   = 0;    // h read buffer
    int par = 0;    // np/gd read buffer

    const ulonglong2* Upk2 = (const ulonglong2*)g_Upk;

    while (s >= 0) {
        const int snext = nxt[s];

        // ---- rs/gate for this step: redundant per warp (lanes lh==0) ----
        if (lh == 0) {
            float ssum = 0.f, gsum = 0.f;
#pragma unroll
            for (int q = 0; q < 8; ++q) {
                ssum += np_sh[par][ll * 8 + q];
                gsum += gd_sh[par][ll * 8 + q];
            }
            float rsv = rsqrtf(fmaxf(ssum, 1e-12f));
            float ek  = __ldg(g_eK + (encRow + s) * Kn + kgbl + ll);
            rs_sh[ll]   = rsv;
            gate_sh[ll] = 1.f / (1.f + expf(-(fmaf(rsv, gsum, ek))));
        }

        // ---- GEMM partial over own d-half: 16 rows x 2 cols x 64 pairs ----
        const float* hb = h[p];
        unsigned long long accA[16], accB[16];
#pragma unroll
        for (int r = 0; r < 16; ++r) { accA[r] = 0ull; accB[r] = 0ull; }

#pragma unroll
        for (int g8 = 0; g8 < 8; ++g8) {
            const int p0 = pbase + g8 * 8;
            ulonglong2 u0 = __ldg(Upk2 + (size_t)(p0 + 0) * 128 + cp);
            ulonglong2 u1 = __ldg(Upk2 + (size_t)(p0 + 1) * 128 + cp);
            ulonglong2 u2 = __ldg(Upk2 + (size_t)(p0 + 2) * 128 + cp);
            ulonglong2 u3 = __ldg(Upk2 + (size_t)(p0 + 3) * 128 + cp);
            ulonglong2 u4 = __ldg(Upk2 + (size_t)(p0 + 4) * 128 + cp);
            ulonglong2 u5 = __ldg(Upk2 + (size_t)(p0 + 5) * 128 + cp);
            ulonglong2 u6 = __ldg(Upk2 + (size_t)(p0 + 6) * 128 + cp);
            ulonglong2 u7 = __ldg(Upk2 + (size_t)(p0 + 7) * 128 + cp);
#pragma unroll
            for (int r = 0; r < 16; ++r) {
                const ulonglong2* hp = (const ulonglong2*)&hb[r * D + p0 * 2];
                ulonglong2 h0 = hp[0], h1 = hp[1], h2 = hp[2], h3 = hp[3];
                FMA_F32X2(accA[r], h0.x, u0.x, accA[r]);
                FMA_F32X2(accB[r], h0.x, u0.y, accB[r]);
                FMA_F32X2(accA[r], h0.y, u1.x, accA[r]);
                FMA_F32X2(accB[r], h0.y, u1.y, accB[r]);
                FMA_F32X2(accA[r], h1.x, u2.x, accA[r]);
                FMA_F32X2(accB[r], h1.x, u2.y, accB[r]);
                FMA_F32X2(accA[r], h1.y, u3.x, accA[r]);
                FMA_F32X2(accB[r], h1.y, u3.y, accB[r]);
                FMA_F32X2(accA[r], h2.x, u4.x, accA[r]);
                FMA_F32X2(accB[r], h2.x, u4.y, accB[r]);
                FMA_F32X2(accA[r], h2.y, u5.x, accA[r]);
                FMA_F32X2(accB[r], h2.y, u5.y, accB[r]);
                FMA_F32X2(accA[r], h3.x, u6.x, accA[r]);
                FMA_F32X2(accB[r], h3.x, u6.y, accB[r]);
                FMA_F32X2(accA[r], h3.y, u7.x, accA[r]);
                FMA_F32X2(accB[r], h3.y, u7.y, accB[r]);
            }
        }

        // collapse + partner swap (keep own 8 rows, swap the other 8)
        float sA[16], sB[16];
#pragma unroll
        for (int r = 0; r < 16; ++r) {
            float2 aA = *(float2*)&accA[r];
            float2 aB = *(float2*)&accB[r];
            sA[r] = aA.x + aA.y;
            sB[r] = aB.x + aB.y;
        }
        float myA[8], myB[8];
#pragma unroll
        for (int j = 0; j < 8; ++j) {
            float keepA = lh ? sA[8 + j] : sA[j];
            float sendA = lh ? sA[j]     : sA[8 + j];
            float keepB = lh ? sB[8 + j] : sB[j];
            float sendB = lh ? sB[j]     : sB[8 + j];
            myA[j] = keepA + __shfl_xor_sync(0xffffffffu, sendA, 16);
            myB[j] = keepB + __shfl_xor_sync(0xffffffffu, sendB, 16);
        }

        // prefetch per-step scalars (hide under epilogue)
        const float2 ew = __ldg((const float2*)(g_encW + (encRow + s) * D + c0));
        float2 en = make_float2(0.f, 0.f);
        if (snext >= 0)
            en = __ldg((const float2*)(g_enc + (encRow + snext) * D + c0));

        __syncwarp();   // own warp's rs_sh/gate_sh writes visible

        // ---- epilogue: rows rb..rb+7 x 2 cols -> h[p^1] ----
        float* hw = h[p ^ 1];
        const int parw = par ^ 1;
        float np[8], gd[8];
#pragma unroll
        for (int j = 0; j < 8; ++j) {
            int   r  = rb + j;
            float rs = rs_sh[r];
            float gt = gate_sh[r];
            float2 hold = *(float2*)&hb[r * D + c0];
            float htA = fmaxf(fmaf(rs, myA[j], kvA[j] + ew.x), 0.f);
            float htB = fmaxf(fmaf(rs, myB[j], kvB[j] + ew.y), 0.f);
            float hA = fmaf(gt, htA, rs * hold.x);
            float hB = fmaf(gt, htB, rs * hold.y);
            *(float2*)&hw[r * D + c0] = make_float2(hA, hB);
            np[j] = fmaf(hA, hA, hB * hB);
            gd[j] = fmaf(en.x, hA, en.y * hB);
        }
#pragma unroll
        for (int o = 8; o > 0; o >>= 1) {
#pragma unroll
            for (int j = 0; j < 8; ++j) {
                np[j] += __shfl_xor_sync(0xffffffffu, np[j], o);
                gd[j] += __shfl_xor_sync(0xffffffffu, gd[j], o);
            }
        }
        if (ll == 0) {
#pragma unroll
            for (int j = 0; j < 8; ++j) {
                np_sh[parw][(rb + j) * 8 + w] = np[j];
                gd_sh[parw][(rb + j) * 8 + w] = gd[j];
            }
        }

        __syncthreads();   // single per-step barrier
        p ^= 1; par ^= 1;
        s = snext;
    }

    // final rs (redundant per warp, benign race; ordered by last barrier)
    if (lh == 0) {
        float ssum = 0.f;
#pragma unroll
        for (int q = 0; q < 8; ++q) ssum += np_sh[par][ll * 8 + q];
        rs_sh[ll] = rsqrtf(fmaxf(ssum, 1e-12f));
    }
    __syncwarp();
#pragma unroll
    for (int j = 0; j < 8; ++j) {
        int r = rb + j;
        float2 hv = *(float2*)&h[p][r * D + c0];
        *(float2*)&out[((size_t)b * Kn + kgbl + r) * D + c0] =
            make_float2(hv.x * rs_sh[r], hv.y * rs_sh[r]);
    }
}

// ---------------------------------------------------------------------------
extern "C" void kernel_launch(void* const* d_in, const int* in_sizes, int n_in,
                              void* d_out, int out_size) {
    const int*   prgrph = (const int*)d_in[0];
    const int*   pmask  = (const int*)d_in[1];
    const float* keys   = (const float*)d_in[2];
    const float* emb    = (const float*)d_in[3];
    const float* U      = (const float*)d_in[4];
    const float* V      = (const float*)d_in[5];
    const float* W      = (const float*)d_in[6];
    float*       out    = (float*)d_out;

    pack_kernel<<<384, 256>>>(U, W, V);
    gather_eK_kernel<<<Bn * Sn, 256>>>(prgrph, emb, keys);
    gemm_pre_kernel<<<768, 256>>>(keys);
    scan_kernel<<<Bn * 2, 256>>>(pmask, out);
}

// round 15
// speedup vs baseline: 1.1865x; 1.0026x over previous
#include <cuda_runtime.h>
#include <cuda_bf16.h>
#include <math.h>

#define VOCAB 50000
#define D 256
#define Bn 128
#define Sn 64
#define Ln 32
#define Kn 32

// Scratch (device globals: allocation-free rule)
__device__ float  g_enc [Bn * Sn * D];          // enc_sents   (B,S,D)
__device__ float  g_encW[Bn * Sn * D];          // enc_sents@W (B,S,D)
__device__ float  g_keysV[Bn * Kn * D];         // keys@V      (B,K,D)
__device__ float  g_eK  [Bn * Sn * Kn];         // enc·keys    (B,S,K)
__device__ float2 g_Upk [(D / 2) * D];          // packed U: [p][c]=(U[2p][c],U[2p+1][c])
__device__ float2 g_Wpk [(D / 2) * D];          // packed W
__device__ float2 g_Vpk [(D / 2) * D];          // packed V

#define FMA_F32X2(d_, a_, b_, c_) \
    asm("fma.rn.f32x2 %0, %1, %2, %3;" : "=l"(d_) : "l"(a_), "l"(b_), "l"(c_))

// ---------------------------------------------------------------------------
// Fused: enc_sents[b,s,d] = sum_l emb[prgrph[b,s,l], d]
//        eK[b,s,k]        = sum_d enc[b,s,d] * keys[b,k,d]
// ---------------------------------------------------------------------------
__global__ void gather_eK_kernel(const int* __restrict__ prgrph,
                                 const float* __restrict__ emb,
                                 const float* __restrict__ keys) {
    __shared__ int   sidx[Ln];
    __shared__ float e_sh[D];
    int bs = blockIdx.x;
    int b  = bs / Sn;
    int t  = threadIdx.x;
    int w  = t >> 5, lane = t & 31;
    if (t < Ln) sidx[t] = prgrph[(size_t)bs * Ln + t];
    __syncthreads();
    float acc = 0.f;
#pragma unroll
    for (int l = 0; l < Ln; ++l) acc += __ldg(emb + (size_t)sidx[l] * D + t);
    g_enc[(size_t)bs * D + t] = acc;
    e_sh[t] = acc;
    __syncthreads();
#pragma unroll
    for (int r = 0; r < 4; ++r) {
        int k = w * 4 + r;
        const float* kr = keys + ((size_t)b * Kn + k) * D;
        float p = 0.f;
#pragma unroll
        for (int j = 0; j < 8; ++j) {
            int c = lane + 32 * j;
            p = fmaf(e_sh[c], __ldg(kr + c), p);
        }
#pragma unroll
        for (int o = 16; o > 0; o >>= 1) p += __shfl_xor_sync(0xffffffffu, p, o);
        if (lane == 0) g_eK[(size_t)bs * Kn + k] = p;
    }
}

// ---------------------------------------------------------------------------
// Pack U, W, V into float2 d-pairs: dst[p*D + c] = (M[2p][c], M[2p+1][c])
// ---------------------------------------------------------------------------
__global__ void pack_kernel(const float* __restrict__ U,
                            const float* __restrict__ W,
                            const float* __restrict__ V) {
    int p     = blockIdx.x & 127;
    int which = blockIdx.x >> 7;
    int c     = threadIdx.x;
    const float* M = (which == 0) ? U : (which == 1) ? W : V;
    float2* dst    = (which == 0) ? g_Upk : (which == 1) ? g_Wpk : g_Vpk;
    dst[p * D + c] = make_float2(M[(2 * p) * D + c], M[(2 * p + 1) * D + c]);
}

// ---------------------------------------------------------------------------
// 16-row GEMM tile in scan style: C[16,D] = A[16,D] @ B[D,D] (B packed f32x2)
// warp w lane l: colpair cp = 16w + (l&15), d-half lh = l>>4.
// ---------------------------------------------------------------------------
__device__ __forceinline__ void gemm16_f32x2(const float* __restrict__ Ab,
                                             const float2* __restrict__ Bpk,
                                             float* __restrict__ Cb) {
    __shared__ float a_sh[16 * D];
    const int t    = threadIdx.x;
    const int w    = t >> 5;
    const int lane = t & 31;
    const int lh   = lane >> 4;
    const int ll   = lane & 15;
    const int cp   = w * 16 + ll;
    const int c0   = cp * 2;
    const int rb   = lh * 8;
    const int pbase = lh * 64;

    for (int i = t; i < 16 * D; i += 256) a_sh[i] = Ab[i];
    __syncthreads();

    unsigned long long accA[16], accB[16];
#pragma unroll
    for (int r = 0; r < 16; ++r) { accA[r] = 0ull; accB[r] = 0ull; }

    const ulonglong2* B2 = (const ulonglong2*)Bpk;
#pragma unroll
    for (int g8 = 0; g8 < 8; ++g8) {
        const int p0 = pbase + g8 * 8;
        ulonglong2 u0 = __ldg(B2 + (size_t)(p0 + 0) * 128 + cp);
        ulonglong2 u1 = __ldg(B2 + (size_t)(p0 + 1) * 128 + cp);
        ulonglong2 u2 = __ldg(B2 + (size_t)(p0 + 2) * 128 + cp);
        ulonglong2 u3 = __ldg(B2 + (size_t)(p0 + 3) * 128 + cp);
        ulonglong2 u4 = __ldg(B2 + (size_t)(p0 + 4) * 128 + cp);
        ulonglong2 u5 = __ldg(B2 + (size_t)(p0 + 5) * 128 + cp);
        ulonglong2 u6 = __ldg(B2 + (size_t)(p0 + 6) * 128 + cp);
        ulonglong2 u7 = __ldg(B2 + (size_t)(p0 + 7) * 128 + cp);
#pragma unroll
        for (int r = 0; r < 16; ++r) {
            const ulonglong2* hp = (const ulonglong2*)&a_sh[r * D + p0 * 2];
            ulonglong2 h0 = hp[0], h1 = hp[1], h2 = hp[2], h3 = hp[3];
            FMA_F32X2(accA[r], h0.x, u0.x, accA[r]);
            FMA_F32X2(accB[r], h0.x, u0.y, accB[r]);
            FMA_F32X2(accA[r], h0.y, u1.x, accA[r]);
            FMA_F32X2(accB[r], h0.y, u1.y, accB[r]);
            FMA_F32X2(accA[r], h1.x, u2.x, accA[r]);
            FMA_F32X2(accB[r], h1.x, u2.y, accB[r]);
            FMA_F32X2(accA[r], h1.y, u3.x, accA[r]);
            FMA_F32X2(accB[r], h1.y, u3.y, accB[r]);
            FMA_F32X2(accA[r], h2.x, u4.x, accA[r]);
            FMA_F32X2(accB[r], h2.x, u4.y, accB[r]);
            FMA_F32X2(accA[r], h2.y, u5.x, accA[r]);
            FMA_F32X2(accB[r], h2.y, u5.y, accB[r]);
            FMA_F32X2(accA[r], h3.x, u6.x, accA[r]);
            FMA_F32X2(accB[r], h3.x, u6.y, accB[r]);
            FMA_F32X2(accA[r], h3.y, u7.x, accA[r]);
            FMA_F32X2(accB[r], h3.y, u7.y, accB[r]);
        }
    }

    float sA[16], sB[16];
#pragma unroll
    for (int r = 0; r < 16; ++r) {
        float2 aA = *(float2*)&accA[r];
        float2 aB = *(float2*)&accB[r];
        sA[r] = aA.x + aA.y;
        sB[r] = aB.x + aB.y;
    }
#pragma unroll
    for (int j = 0; j < 8; ++j) {
        float keepA = lh ? sA[8 + j] : sA[j];
        float sendA = lh ? sA[j]     : sA[8 + j];
        float keepB = lh ? sB[8 + j] : sB[j];
        float sendB = lh ? sB[j]     : sB[8 + j];
        float mA = keepA + __shfl_xor_sync(0xffffffffu, sendA, 16);
        float mB = keepB + __shfl_xor_sync(0xffffffffu, sendB, 16);
        *(float2*)&Cb[(rb + j) * D + c0] = make_float2(mA, mB);
    }
}

// encW tiles (0..511) + keysV tiles (512..767)
__global__ void gemm_pre_kernel(const float* __restrict__ keys) {
    int blk = blockIdx.x;
    if (blk < 512) {
        size_t off = (size_t)blk * 16 * D;
        gemm16_f32x2(g_enc + off, g_Wpk, g_encW + off);
    } else {
        size_t off = (size_t)(blk - 512) * 16 * D;
        gemm16_f32x2(keys + off, g_Vpk, g_keysV + off);
    }
}

// ---------------------------------------------------------------------------
// The scan. 256 CTAs = (batch, 16-row half). 256 threads, 2 CTAs/SM.
// Warp w lane l: colpair cp = 16w + (l&15); d-half lh = l>>4.
// Single __syncthreads per step:
//   - h double-buffered (GEMM reads h[p], epilogue writes h[p^1])
//   - np/gd partial buffers double-buffered by step parity
//   - rs/gate computed redundantly per warp from np/gd (benign identical-value
//     races on rs_sh/gate_sh), ordered by __syncwarp placed after the GEMM so
//     the eK load + expf latency hides under it.
// Partner-swap combine: 16 shfl_xor(16) instead of full 32-row exchange.
// h kept UNNORMALIZED; rs folded into gate/epilogue/output.
// ---------------------------------------------------------------------------
#define KH 16

__global__ void __launch_bounds__(256, 2)
scan_kernel(const int* __restrict__ pmask,
            float* __restrict__ out) {
    __shared__ float h[2][KH * D];        // 2 x 16 KB, unnormalized local rows
    __shared__ float np_sh[2][KH * 8];
    __shared__ float gd_sh[2][KH * 8];
    __shared__ float rs_sh[KH];           // benign-race (identical values)
    __shared__ float gate_sh[KH];
    __shared__ int   nxt[Sn + 1];

    const int b    = blockIdx.x >> 1;
    const int half = blockIdx.x & 1;
    const int kgbl = half * KH;
    const int t    = threadIdx.x;
    const int w    = t >> 5;
    const int lane = t & 31;
    const int lh   = lane >> 4;
    const int ll   = lane & 15;
    const int cp   = w * 16 + ll;
    const int c0   = cp * 2;
    const int rb   = lh * 8;
    const int pbase = lh * 64;

    const size_t encRow = (size_t)b * Sn;

    if (t == 0) {
        int n = -1;
        for (int s = Sn - 1; s >= 0; --s) {
            nxt[s] = n;
            if (pmask[(encRow + s) * Ln] != 0) n = s;
        }
        nxt[Sn] = n;
    }
    float kvA[8], kvB[8];
#pragma unroll
    for (int j = 0; j < 8; ++j) {
        float2 kv = __ldg((const float2*)
            (g_keysV + ((size_t)b * Kn + kgbl + rb + j) * D + c0));
        kvA[j] = kv.x; kvB[j] = kv.y;
    }
    for (int i = t; i < KH * D; i += 256) h[0][i] = 0.f;
    for (int i = t; i < KH * 8; i += 256) { np_sh[0][i] = 0.125f; gd_sh[0][i] = 0.f; }
    __syncthreads();

    int s   = nxt[Sn];
    int p   = 0;    // h read buffer
    int par = 0;    // np/gd read buffer

    const ulonglong2* Upk2 = (const ulonglong2*)g_Upk;

    while (s >= 0) {
        const int snext = nxt[s];

        // ---- rs/gate for this step: redundant per warp (lanes lh==0) ----
        if (lh == 0) {
            float ssum = 0.f, gsum = 0.f;
#pragma unroll
            for (int q = 0; q < 8; ++q) {
                ssum += np_sh[par][ll * 8 + q];
                gsum += gd_sh[par][ll * 8 + q];
            }
            float rsv = rsqrtf(fmaxf(ssum, 1e-12f));
            float ek  = __ldg(g_eK + (encRow + s) * Kn + kgbl + ll);
            rs_sh[ll]   = rsv;
            gate_sh[ll] = 1.f / (1.f + expf(-(fmaf(rsv, gsum, ek))));
        }

        // ---- GEMM partial over own d-half: 16 rows x 2 cols x 64 pairs ----
        const float* hb = h[p];
        unsigned long long accA[16], accB[16];
#pragma unroll
        for (int r = 0; r < 16; ++r) { accA[r] = 0ull; accB[r] = 0ull; }

#pragma unroll
        for (int g8 = 0; g8 < 8; ++g8) {
            const int p0 = pbase + g8 * 8;
            ulonglong2 u0 = __ldg(Upk2 + (size_t)(p0 + 0) * 128 + cp);
            ulonglong2 u1 = __ldg(Upk2 + (size_t)(p0 + 1) * 128 + cp);
            ulonglong2 u2 = __ldg(Upk2 + (size_t)(p0 + 2) * 128 + cp);
            ulonglong2 u3 = __ldg(Upk2 + (size_t)(p0 + 3) * 128 + cp);
            ulonglong2 u4 = __ldg(Upk2 + (size_t)(p0 + 4) * 128 + cp);
            ulonglong2 u5 = __ldg(Upk2 + (size_t)(p0 + 5) * 128 + cp);
            ulonglong2 u6 = __ldg(Upk2 + (size_t)(p0 + 6) * 128 + cp);
            ulonglong2 u7 = __ldg(Upk2 + (size_t)(p0 + 7) * 128 + cp);
#pragma unroll
            for (int r = 0; r < 16; ++r) {
                const ulonglong2* hp = (const ulonglong2*)&hb[r * D + p0 * 2];
                ulonglong2 h0 = hp[0], h1 = hp[1], h2 = hp[2], h3 = hp[3];
                FMA_F32X2(accA[r], h0.x, u0.x, accA[r]);
                FMA_F32X2(accB[r], h0.x, u0.y, accB[r]);
                FMA_F32X2(accA[r], h0.y, u1.x, accA[r]);
                FMA_F32X2(accB[r], h0.y, u1.y, accB[r]);
                FMA_F32X2(accA[r], h1.x, u2.x, accA[r]);
                FMA_F32X2(accB[r], h1.x, u2.y, accB[r]);
                FMA_F32X2(accA[r], h1.y, u3.x, accA[r]);
                FMA_F32X2(accB[r], h1.y, u3.y, accB[r]);
                FMA_F32X2(accA[r], h2.x, u4.x, accA[r]);
                FMA_F32X2(accB[r], h2.x, u4.y, accB[r]);
                FMA_F32X2(accA[r], h2.y, u5.x, accA[r]);
                FMA_F32X2(accB[r], h2.y, u5.y, accB[r]);
                FMA_F32X2(accA[r], h3.x, u6.x, accA[r]);
                FMA_F32X2(accB[r], h3.x, u6.y, accB[r]);
                FMA_F32X2(accA[r], h3.y, u7.x, accA[r]);
                FMA_F32X2(accB[r], h3.y, u7.y, accB[r]);
            }
        }

        // collapse + partner swap (keep own 8 rows, swap the other 8)
        float sA[16], sB[16];
#pragma unroll
        for (int r = 0; r < 16; ++r) {
            float2 aA = *(float2*)&accA[r];
            float2 aB = *(float2*)&accB[r];
            sA[r] = aA.x + aA.y;
            sB[r] = aB.x + aB.y;
        }
        float myA[8], myB[8];
#pragma unroll
        for (int j = 0; j < 8; ++j) {
            float keepA = lh ? sA[8 + j] : sA[j];
            float sendA = lh ? sA[j]     : sA[8 + j];
            float keepB = lh ? sB[8 + j] : sB[j];
            float sendB = lh ? sB[j]     : sB[8 + j];
            myA[j] = keepA + __shfl_xor_sync(0xffffffffu, sendA, 16);
            myB[j] = keepB + __shfl_xor_sync(0xffffffffu, sendB, 16);
        }

        // prefetch per-step scalars (hide under epilogue)
        const float2 ew = __ldg((const float2*)(g_encW + (encRow + s) * D + c0));
        float2 en = make_float2(0.f, 0.f);
        if (snext >= 0)
            en = __ldg((const float2*)(g_enc + (encRow + snext) * D + c0));

        __syncwarp();   // own warp's rs_sh/gate_sh writes visible

        // ---- epilogue: rows rb..rb+7 x 2 cols -> h[p^1] ----
        float* hw = h[p ^ 1];
        const int parw = par ^ 1;
        float np[8], gd[8];
#pragma unroll
        for (int j = 0; j < 8; ++j) {
            int   r  = rb + j;
            float rs = rs_sh[r];
            float gt = gate_sh[r];
            float2 hold = *(float2*)&hb[r * D + c0];
            float htA = fmaxf(fmaf(rs, myA[j], kvA[j] + ew.x), 0.f);
            float htB = fmaxf(fmaf(rs, myB[j], kvB[j] + ew.y), 0.f);
            float hA = fmaf(gt, htA, rs * hold.x);
            float hB = fmaf(gt, htB, rs * hold.y);
            *(float2*)&hw[r * D + c0] = make_float2(hA, hB);
            np[j] = fmaf(hA, hA, hB * hB);
            gd[j] = fmaf(en.x, hA, en.y * hB);
        }
#pragma unroll
        for (int o = 8; o > 0; o >>= 1) {
#pragma unroll
            for (int j = 0; j < 8; ++j) {
                np[j] += __shfl_xor_sync(0xffffffffu, np[j], o);
                gd[j] += __shfl_xor_sync(0xffffffffu, gd[j], o);
            }
        }
        if (ll == 0) {
#pragma unroll
            for (int j = 0; j < 8; ++j) {
                np_sh[parw][(rb + j) * 8 + w] = np[j];
                gd_sh[parw][(rb + j) * 8 + w] = gd[j];
            }
        }

        __syncthreads();   // single per-step barrier
        p ^= 1; par ^= 1;
        s = snext;
    }

    // final rs (redundant per warp, benign race; ordered by last barrier)
    if (lh == 0) {
        float ssum = 0.f;
#pragma unroll
        for (int q = 0; q < 8; ++q) ssum += np_sh[par][ll * 8 + q];
        rs_sh[ll] = rsqrtf(fmaxf(ssum, 1e-12f));
    }
    __syncwarp();
#pragma unroll
    for (int j = 0; j < 8; ++j) {
        int r = rb + j;
        float2 hv = *(float2*)&h[p][r * D + c0];
        *(float2*)&out[((size_t)b * Kn + kgbl + r) * D + c0] =
            make_float2(hv.x * rs_sh[r], hv.y * rs_sh[r]);
    }
}

// ---------------------------------------------------------------------------
extern "C" void kernel_launch(void* const* d_in, const int* in_sizes, int n_in,
                              void* d_out, int out_size) {
    const int*   prgrph = (const int*)d_in[0];
    const int*   pmask  = (const int*)d_in[1];
    const float* keys   = (const float*)d_in[2];
    const float* emb    = (const float*)d_in[3];
    const float* U      = (const float*)d_in[4];
    const float* V      = (const float*)d_in[5];
    const float* W      = (const float*)d_in[6];
    float*       out    = (float*)d_out;

    pack_kernel<<<384, 256>>>(U, W, V);
    gather_eK_kernel<<<Bn * Sn, 256>>>(prgrph, emb, keys);
    gemm_pre_kernel<<<768, 256>>>(keys);
    scan_kernel<<<Bn * 2, 256>>>(pmask, out);
}